// round 1
// baseline (speedup 1.0000x reference)
#include <cuda_runtime.h>

// Fixed problem shapes
#define N_IMG 48
#define Hc 128
#define Wc 128

// Scratch (allocation-free rule: __device__ globals)
__device__ float g_y1[48u * 128u * 128u * 128u];  // conv1 out [48,128,128,128]
__device__ float g_y2[48u * 32u * 128u * 128u];   // conv2 out [48,32,128,128]

// ---------------------------------------------------------------------------
// Direct 3x3 conv, stride 1, pad 1, NCHW. Block: 256 threads, 32x32 pixel
// tile, 8 output channels. IC chunked by 4 through shared memory.
// Each thread: 2x2 pixels spread by +16 (conflict-free LDS, coalesced STG)
// x 8 oc = 32 fp32 accumulators. Per (ic,ky,kx): 12 LDS + 32 FFMA -> FMA bound.
// ---------------------------------------------------------------------------
template<int IC, int OC, bool RELU>
__device__ __forceinline__ void conv3x3_tile(
    const float* __restrict__ x, const float* __restrict__ w,
    const float* __restrict__ bias, float* __restrict__ y)
{
    __shared__ float sx[4][34][34];
    __shared__ float sw[8][4][9];

    const int tid = threadIdx.x;
    const int tx = tid & 15, ty = tid >> 4;
    const int tileY = (blockIdx.x >> 2) << 5;   // 4x4 tiles of 32x32
    const int tileX = (blockIdx.x & 3) << 5;
    const int ocb = blockIdx.y << 3;            // 8 oc per block
    const int n = blockIdx.z;

    float acc[8][4];
#pragma unroll
    for (int o = 0; o < 8; o++)
#pragma unroll
        for (int p = 0; p < 4; p++) acc[o][p] = 0.f;

    const float* xn = x + (size_t)n * IC * (Hc * Wc);

    for (int ic0 = 0; ic0 < IC; ic0 += 4) {
        __syncthreads();
        // stage 4-channel input tile with halo (zero padded)
        for (int e = tid; e < 4 * 34 * 34; e += 256) {
            int ic = e / (34 * 34);
            int r = (e / 34) % 34;
            int c = e % 34;
            int gy = tileY - 1 + r, gx = tileX - 1 + c;
            float v = 0.f;
            if ((unsigned)gy < (unsigned)Hc && (unsigned)gx < (unsigned)Wc)
                v = xn[(size_t)(ic0 + ic) * (Hc * Wc) + gy * Wc + gx];
            sx[ic][r][c] = v;
        }
        // stage weights for 8 oc x 4 ic x 9
        for (int e = tid; e < 8 * 4 * 9; e += 256) {
            int o = e / 36, rem = e % 36;
            sw[o][rem / 9][rem % 9] =
                w[((size_t)(ocb + o) * IC + ic0 + rem / 9) * 9 + rem % 9];
        }
        __syncthreads();

#pragma unroll
        for (int ic = 0; ic < 4; ic++) {
#pragma unroll
            for (int ky = 0; ky < 3; ky++) {
#pragma unroll
                for (int kx = 0; kx < 3; kx++) {
                    float wv[8];
#pragma unroll
                    for (int o = 0; o < 8; o++) wv[o] = sw[o][ic][ky * 3 + kx];
                    float x00 = sx[ic][ty + ky][tx + kx];
                    float x01 = sx[ic][ty + ky][tx + 16 + kx];
                    float x10 = sx[ic][ty + 16 + ky][tx + kx];
                    float x11 = sx[ic][ty + 16 + ky][tx + 16 + kx];
#pragma unroll
                    for (int o = 0; o < 8; o++) {
                        acc[o][0] = fmaf(wv[o], x00, acc[o][0]);
                        acc[o][1] = fmaf(wv[o], x01, acc[o][1]);
                        acc[o][2] = fmaf(wv[o], x10, acc[o][2]);
                        acc[o][3] = fmaf(wv[o], x11, acc[o][3]);
                    }
                }
            }
        }
    }

#pragma unroll
    for (int o = 0; o < 8; o++) {
        float bv = bias[ocb + o];
        float* yp = y + (size_t)(n * OC + ocb + o) * (Hc * Wc);
        int py = tileY + ty, px = tileX + tx;
        float v0 = acc[o][0] + bv, v1 = acc[o][1] + bv;
        float v2 = acc[o][2] + bv, v3 = acc[o][3] + bv;
        if (RELU) {
            v0 = fmaxf(v0, 0.f); v1 = fmaxf(v1, 0.f);
            v2 = fmaxf(v2, 0.f); v3 = fmaxf(v3, 0.f);
        }
        yp[py * Wc + px]             = v0;
        yp[py * Wc + px + 16]        = v1;
        yp[(py + 16) * Wc + px]      = v2;
        yp[(py + 16) * Wc + px + 16] = v3;
    }
}

__global__ __launch_bounds__(256) void conv1_k(
    const float* __restrict__ x, const float* __restrict__ w,
    const float* __restrict__ b)
{
    conv3x3_tile<64, 128, true>(x, w, b, g_y1);
}

__global__ __launch_bounds__(256) void conv2_k(
    const float* __restrict__ w, const float* __restrict__ b)
{
    conv3x3_tile<128, 32, true>(g_y1, w, b, g_y2);
}

// ---------------------------------------------------------------------------
// Fused: bilinear x2 upsample (half-pixel centers, edge clamp) + 3x3 conv
// (zero pad) 32->1. Never materializes the 400MB upsampled tensor.
// Per block: 16x16 output tile. v-tile (clamped) -> u-tile (zero padded
// outside [0,256)) in smem -> 3x3x32 conv from smem.
// For u index t: even t=2j -> src between v[j-1],v[j] w (0.25,0.75);
//                odd  t=2j+1 -> v[j],v[j+1] w (0.75,0.25).
// ---------------------------------------------------------------------------
__global__ __launch_bounds__(256) void upconv3_k(
    const float* __restrict__ w3, const float* __restrict__ b3,
    float* __restrict__ out)
{
    __shared__ float sv[16][10][10];
    __shared__ float su[16][18][18];
    __shared__ float sw3[288];

    const int tid = threadIdx.x;
    const int tx = tid & 15, ty = tid >> 4;
    const int tileY = (blockIdx.x >> 4) << 4;   // 16x16 tiles of 16x16
    const int tileX = (blockIdx.x & 15) << 4;
    const int n = blockIdx.y;
    const int m0 = tileY >> 1, q0 = tileX >> 1;

    for (int e = tid; e < 288; e += 256) sw3[e] = w3[e];

    float acc = 0.f;
    for (int c0 = 0; c0 < 32; c0 += 16) {
        __syncthreads();
        // clamped v tile: rows m0-1..m0+8, cols q0-1..q0+8, 16 channels
        for (int e = tid; e < 16 * 10 * 10; e += 256) {
            int ic = e / 100, r = (e / 10) % 10, c = e % 10;
            int gy = min(max(m0 - 1 + r, 0), Hc - 1);
            int gx = min(max(q0 - 1 + c, 0), Wc - 1);
            sv[ic][r][c] =
                g_y2[((size_t)(n * 32 + c0 + ic) * Hc + gy) * Wc + gx];
        }
        __syncthreads();
        // u tile with conv3 zero padding folded in
        for (int e = tid; e < 16 * 18 * 18; e += 256) {
            int ic = e / 324, r = (e / 18) % 18, c = e % 18;
            int tyg = tileY - 1 + r, txg = tileX - 1 + c;
            float uv = 0.f;
            if ((unsigned)tyg < 256u && (unsigned)txg < 256u) {
                int i0y, i0x; float fy, fx;
                if (tyg & 1) { i0y = tyg >> 1;       fy = 0.25f; }
                else         { i0y = (tyg >> 1) - 1; fy = 0.75f; }
                if (txg & 1) { i0x = txg >> 1;       fx = 0.25f; }
                else         { i0x = (txg >> 1) - 1; fx = 0.75f; }
                int ly = i0y - (m0 - 1), lx = i0x - (q0 - 1);
                float v00 = sv[ic][ly][lx],     v01 = sv[ic][ly][lx + 1];
                float v10 = sv[ic][ly + 1][lx], v11 = sv[ic][ly + 1][lx + 1];
                float gy1 = 1.f - fy, gx1 = 1.f - fx;
                uv = gy1 * (gx1 * v00 + fx * v01) + fy * (gx1 * v10 + fx * v11);
            }
            su[ic][r][c] = uv;
        }
        __syncthreads();
#pragma unroll
        for (int ic = 0; ic < 16; ic++)
#pragma unroll
            for (int dy = 0; dy < 3; dy++)
#pragma unroll
                for (int dx = 0; dx < 3; dx++)
                    acc = fmaf(sw3[(c0 + ic) * 9 + dy * 3 + dx],
                               su[ic][ty + dy][tx + dx], acc);
    }
    acc += b3[0];
    out[((size_t)(n * 256) + tileY + ty) * 256 + tileX + tx] = acc;
}

// ---------------------------------------------------------------------------
extern "C" void kernel_launch(void* const* d_in, const int* in_sizes, int n_in,
                              void* d_out, int out_size)
{
    const float* x  = (const float*)d_in[0];
    // d_in[1] = to_process (identity arange), d_in[2] = batch_size: no-ops
    const float* W1 = (const float*)d_in[3];
    const float* b1 = (const float*)d_in[4];
    const float* W2 = (const float*)d_in[5];
    const float* b2 = (const float*)d_in[6];
    const float* W3 = (const float*)d_in[7];
    const float* b3 = (const float*)d_in[8];
    float* out = (float*)d_out;

    conv1_k<<<dim3(16, 16, N_IMG), 256>>>(x, W1, b1);
    conv2_k<<<dim3(16, 4, N_IMG), 256>>>(W2, b2);
    upconv3_k<<<dim3(256, N_IMG), 256>>>(W3, b3, out);
}